// round 5
// baseline (speedup 1.0000x reference)
#include <cuda_runtime.h>
#include <math.h>

// Problem constants (match reference setup_inputs)
#define N_EDGES   800000
#define N_NODES   50000
#define D_FEAT    128
#define NEG_SLOPE 0.2f

// Scratch: per-node softmax denominator (later holds its reciprocal).
// __device__ global => no allocation, allowed by harness rules.
__device__ float d_seg_sum[N_NODES];

// ---------------------------------------------------------------------------
// K0: zero the per-node accumulators (must run every replay of the graph).
// ---------------------------------------------------------------------------
__global__ void k_init() {
    int i = blockIdx.x * blockDim.x + threadIdx.x;
    if (i < N_NODES) d_seg_sum[i] = 0.0f;
}

// ---------------------------------------------------------------------------
// K1: per-edge logit = LeakyReLU(x[e,:]·W + b); e = exp(logit);
//     out[e] = e;  atomicAdd(seg_sum[index[e]], e)
//
// One warp handles 4 edges: each lane loads one float4 per edge
// (32 lanes * 4 floats = 128 = D_FEAT); 4 independent loads in flight
// per lane before any reduction. Butterfly shuffle-reduce per edge.
// ---------------------------------------------------------------------------
__global__ __launch_bounds__(256) void k_logits(
    const float* __restrict__ x,
    const float* __restrict__ W,
    const float* __restrict__ b,
    const int*   __restrict__ index,   // int32! (jax x64 disabled)
    float* __restrict__ out)
{
    constexpr int EPW = 4;                       // edges per warp
    const int lane = threadIdx.x & 31;
    const int warp = blockIdx.x * (blockDim.x >> 5) + (threadIdx.x >> 5);
    const long long base_e = (long long)warp * EPW;
    if (base_e >= N_EDGES) return;

    // W is tiny (512 B) -> L1/L2 resident broadcast
    const float4 wv = *reinterpret_cast<const float4*>(W + lane * 4);

    float acc0, acc1, acc2, acc3;
    {
        // Issue all 4 row loads back-to-back (independent -> MLP=4/lane)
        const float* xp = x + base_e * D_FEAT + lane * 4;
        float4 x0 = *reinterpret_cast<const float4*>(xp + 0 * D_FEAT);
        float4 x1 = *reinterpret_cast<const float4*>(xp + 1 * D_FEAT);
        float4 x2 = *reinterpret_cast<const float4*>(xp + 2 * D_FEAT);
        float4 x3 = *reinterpret_cast<const float4*>(xp + 3 * D_FEAT);
        acc0 = fmaf(x0.x, wv.x, fmaf(x0.y, wv.y, fmaf(x0.z, wv.z, x0.w * wv.w)));
        acc1 = fmaf(x1.x, wv.x, fmaf(x1.y, wv.y, fmaf(x1.z, wv.z, x1.w * wv.w)));
        acc2 = fmaf(x2.x, wv.x, fmaf(x2.y, wv.y, fmaf(x2.z, wv.z, x2.w * wv.w)));
        acc3 = fmaf(x3.x, wv.x, fmaf(x3.y, wv.y, fmaf(x3.z, wv.z, x3.w * wv.w)));
    }

#pragma unroll
    for (int o = 16; o > 0; o >>= 1) {
        acc0 += __shfl_xor_sync(0xffffffffu, acc0, o);
        acc1 += __shfl_xor_sync(0xffffffffu, acc1, o);
        acc2 += __shfl_xor_sync(0xffffffffu, acc2, o);
        acc3 += __shfl_xor_sync(0xffffffffu, acc3, o);
    }

    if (lane < EPW) {
        float r = acc0;
        if (lane == 1) r = acc1;
        else if (lane == 2) r = acc2;
        else if (lane == 3) r = acc3;

        const long long e = base_e + lane;   // N_EDGES % EPW == 0, always valid
        r += b[0];
        r = (r >= 0.0f) ? r : NEG_SLOPE * r;
        const float ex = expf(r);
        out[e] = ex;
        atomicAdd(&d_seg_sum[index[e]], ex);
    }
}

// ---------------------------------------------------------------------------
// K2: seg_sum <- 1/seg_sum (full-precision divide, 50k elems)
// ---------------------------------------------------------------------------
__global__ void k_recip() {
    int i = blockIdx.x * blockDim.x + threadIdx.x;
    if (i < N_NODES) {
        float s = d_seg_sum[i];
        d_seg_sum[i] = (s > 0.0f) ? (1.0f / s) : 0.0f;
    }
}

// ---------------------------------------------------------------------------
// K3: out[e] *= seg_sum_recip[index[e]]   (seg_sum: 200 KB -> L2 resident)
// ---------------------------------------------------------------------------
__global__ __launch_bounds__(256) void k_norm(
    const int* __restrict__ index,
    float* __restrict__ out)
{
    int e = blockIdx.x * blockDim.x + threadIdx.x;
    if (e < N_EDGES) {
        out[e] = out[e] * __ldg(&d_seg_sum[index[e]]);
    }
}

// ---------------------------------------------------------------------------
extern "C" void kernel_launch(void* const* d_in, const int* in_sizes, int n_in,
                              void* d_out, int out_size) {
    const float* x     = (const float*)d_in[0];  // [800000, 128] f32
    const float* W     = (const float*)d_in[1];  // [128, 1] f32
    const float* b     = (const float*)d_in[2];  // [1] f32
    const int*   index = (const int*)d_in[3];    // [800000] int32 (jax demotes int64)
    float* out = (float*)d_out;                  // [800000] f32

    (void)in_sizes; (void)n_in; (void)out_size;

    // K0: zero accumulators
    k_init<<<(N_NODES + 255) / 256, 256>>>();

    // K1: logits + exp + segment-sum. 256 thr = 8 warps = 32 edges/block.
    const int edges_per_block = 8 * 4;
    const int nblk = (N_EDGES + edges_per_block - 1) / edges_per_block; // 25000
    k_logits<<<nblk, 256>>>(x, W, b, index, out);

    // K2: reciprocal of denominators
    k_recip<<<(N_NODES + 255) / 256, 256>>>();

    // K3: normalize
    k_norm<<<(N_EDGES + 255) / 256, 256>>>(index, out);
}

// round 7
// speedup vs baseline: 1.0050x; 1.0050x over previous
#include <cuda_runtime.h>
#include <math.h>

// Problem constants (match reference setup_inputs)
#define N_EDGES   800000
#define N_NODES   50000
#define D_FEAT    128
#define NEG_SLOPE 0.2f

// Scratch (zero-initialized at module load; d_seg_sum is re-zeroed by
// k_recip_clear each run so every graph replay starts from zeros).
__device__ float d_seg_sum[N_NODES];
__device__ float d_seg_rcp[N_NODES];

// ---------------------------------------------------------------------------
// K1: per-edge logit = LeakyReLU(x[e,:]·W + b); e = exp(logit);
//     out[e] = e;  atomicAdd(seg_sum[index[e]], e)
// One warp handles 4 edges: lane loads one float4 per edge (32*4 = 128).
// ---------------------------------------------------------------------------
__global__ __launch_bounds__(256) void k_logits(
    const float* __restrict__ x,
    const float* __restrict__ W,
    const float* __restrict__ b,
    const int*   __restrict__ index,   // int32 (jax x64 disabled)
    float* __restrict__ out)
{
    constexpr int EPW = 4;                       // edges per warp
    const int lane = threadIdx.x & 31;
    const int warp = blockIdx.x * (blockDim.x >> 5) + (threadIdx.x >> 5);
    const long long base_e = (long long)warp * EPW;
    if (base_e >= N_EDGES) return;

    const float4 wv = *reinterpret_cast<const float4*>(W + lane * 4);

    float acc0, acc1, acc2, acc3;
    {
        const float* xp = x + base_e * D_FEAT + lane * 4;
        float4 x0 = *reinterpret_cast<const float4*>(xp + 0 * D_FEAT);
        float4 x1 = *reinterpret_cast<const float4*>(xp + 1 * D_FEAT);
        float4 x2 = *reinterpret_cast<const float4*>(xp + 2 * D_FEAT);
        float4 x3 = *reinterpret_cast<const float4*>(xp + 3 * D_FEAT);
        acc0 = fmaf(x0.x, wv.x, fmaf(x0.y, wv.y, fmaf(x0.z, wv.z, x0.w * wv.w)));
        acc1 = fmaf(x1.x, wv.x, fmaf(x1.y, wv.y, fmaf(x1.z, wv.z, x1.w * wv.w)));
        acc2 = fmaf(x2.x, wv.x, fmaf(x2.y, wv.y, fmaf(x2.z, wv.z, x2.w * wv.w)));
        acc3 = fmaf(x3.x, wv.x, fmaf(x3.y, wv.y, fmaf(x3.z, wv.z, x3.w * wv.w)));
    }

#pragma unroll
    for (int o = 16; o > 0; o >>= 1) {
        acc0 += __shfl_xor_sync(0xffffffffu, acc0, o);
        acc1 += __shfl_xor_sync(0xffffffffu, acc1, o);
        acc2 += __shfl_xor_sync(0xffffffffu, acc2, o);
        acc3 += __shfl_xor_sync(0xffffffffu, acc3, o);
    }

    if (lane < EPW) {
        float r = acc0;
        if (lane == 1) r = acc1;
        else if (lane == 2) r = acc2;
        else if (lane == 3) r = acc3;

        const long long e = base_e + lane;   // N_EDGES % EPW == 0
        r += b[0];
        r = (r >= 0.0f) ? r : NEG_SLOPE * r;
        const float ex = expf(r);
        out[e] = ex;
        atomicAdd(&d_seg_sum[index[e]], ex);
    }
}

// ---------------------------------------------------------------------------
// K2: d_seg_rcp <- 1/d_seg_sum, and re-zero d_seg_sum for the next replay.
//     (d_seg_sum starts zeroed by static init on the very first call.)
// ---------------------------------------------------------------------------
__global__ void k_recip_clear() {
    int i = blockIdx.x * blockDim.x + threadIdx.x;
    if (i < N_NODES) {
        float s = d_seg_sum[i];
        d_seg_rcp[i] = (s > 0.0f) ? (1.0f / s) : 0.0f;
        d_seg_sum[i] = 0.0f;
    }
}

// ---------------------------------------------------------------------------
// K3: out[e] *= seg_rcp[index[e]], 4 edges per thread (vector loads, MLP=4).
//     N_EDGES % 4 == 0, so no tail handling needed.
// ---------------------------------------------------------------------------
__global__ __launch_bounds__(256) void k_norm4(
    const int* __restrict__ index,
    float* __restrict__ out)
{
    const int t = blockIdx.x * blockDim.x + threadIdx.x;
    const int e4 = t * 4;
    if (e4 >= N_EDGES) return;

    int4   idx = *reinterpret_cast<const int4*>(index + e4);
    float4 o   = *reinterpret_cast<const float4*>(out + e4);

    // 4 independent L2-resident gathers in flight
    float r0 = __ldg(&d_seg_rcp[idx.x]);
    float r1 = __ldg(&d_seg_rcp[idx.y]);
    float r2 = __ldg(&d_seg_rcp[idx.z]);
    float r3 = __ldg(&d_seg_rcp[idx.w]);

    o.x *= r0; o.y *= r1; o.z *= r2; o.w *= r3;
    *reinterpret_cast<float4*>(out + e4) = o;
}

// ---------------------------------------------------------------------------
extern "C" void kernel_launch(void* const* d_in, const int* in_sizes, int n_in,
                              void* d_out, int out_size) {
    const float* x     = (const float*)d_in[0];  // [800000, 128] f32
    const float* W     = (const float*)d_in[1];  // [128, 1] f32
    const float* b     = (const float*)d_in[2];  // [1] f32
    const int*   index = (const int*)d_in[3];    // [800000] int32
    float* out = (float*)d_out;                  // [800000] f32

    (void)in_sizes; (void)n_in; (void)out_size;

    // K1: logits + exp + segment-sum. 256 thr = 8 warps = 32 edges/block.
    const int edges_per_block = 8 * 4;
    const int nblk = (N_EDGES + edges_per_block - 1) / edges_per_block; // 25000
    k_logits<<<nblk, 256>>>(x, W, b, index, out);

    // K2: reciprocal + clear accumulators for next replay
    k_recip_clear<<<(N_NODES + 255) / 256, 256>>>();

    // K3: normalize, 4 edges/thread -> 200k threads
    const int n_thr = N_EDGES / 4;
    k_norm4<<<(n_thr + 255) / 256, 256>>>(index, out);
}